// round 3
// baseline (speedup 1.0000x reference)
#include <cuda_runtime.h>
#include <cuda_bf16.h>

#define BN 8192
#define MARGIN 1.0f
#define TI 256              // threads per block == i-rows per block
#define TJ 1024             // j entries per shared tile
#define GX (BN / TI)        // 32
#define GY (BN / TJ)        // 8
#define NBLK (GX * GY)      // 256 total blocks in k_main

// Allocation-free scratch: __device__ globals (zero-initialized at module load;
// the finalizing block resets them after every call, so each call sees zeros).
__device__ float    g_sum;
__device__ int      g_cnt;
__device__ int      g_nc;
__device__ unsigned g_ticket;
__device__ float    c_risk[BN];
__device__ float    c_time[BN];

// Compact rows with event==1 into c_risk/c_time (order irrelevant for the sum).
__global__ void k_compact(const float* __restrict__ risk,
                          const float* __restrict__ timev,
                          const int*   __restrict__ event) {
    int idx = blockIdx.x * blockDim.x + threadIdx.x;
    if (idx >= BN) return;                      // BN % 32 == 0, warps stay full
    bool p = (event[idx] == 1);
    unsigned m = __ballot_sync(0xFFFFFFFFu, p);
    int lane   = threadIdx.x & 31;
    int leader = __ffs(m) - 1;
    int base = 0;
    if (m != 0u && lane == leader)
        base = atomicAdd(&g_nc, __popc(m));
    base = __shfl_sync(0xFFFFFFFFu, base, (leader < 0 ? 0 : leader));
    if (p) {
        int pos = base + __popc(m & ((1u << lane) - 1u));
        c_risk[pos] = risk[idx];
        c_time[pos] = timev[idx];
    }
}

__global__ void __launch_bounds__(TI)
k_main(const float* __restrict__ risk,
       const float* __restrict__ timev,
       float* __restrict__ out) {
    __shared__ __align__(16) float2 sj[TJ];
    __shared__ float ws[TI / 32];
    __shared__ int   wc[TI / 32];

    const int  nc     = g_nc;
    const bool active = (blockIdx.x * TI) < nc;   // uniform per block

    if (active) {
        // Stage this block's j-tile: (risk_j, time_j)
        const int j0 = blockIdx.y * TJ;
        for (int t = threadIdx.x; t < TJ; t += TI)
            sj[t] = make_float2(risk[j0 + t], timev[j0 + t]);
        __syncthreads();

        const int i = blockIdx.x * TI + threadIdx.x;

        float s[4] = {0.f, 0.f, 0.f, 0.f};
        int   c[4] = {0, 0, 0, 0};

        if (i < nc) {
            const float pr = MARGIN + c_risk[i];   // hinge = max(pr - risk_j, 0)
            const float ti = c_time[i];
            const float4* sj4 = reinterpret_cast<const float4*>(sj);
            // TJ/2 float4 entries, 2 (risk,time) pairs each; U=8 -> 16 pairs/iter
            for (int j = 0; j < TJ / 2; j += 8) {
                #pragma unroll
                for (int u = 0; u < 8; ++u) {
                    float4 v = sj4[j + u];          // (r0, t0, r1, t1) broadcast LDS.128
                    bool  m0 = ti < v.y;
                    bool  m1 = ti < v.w;
                    float h0 = fmaxf(pr - v.x, 0.0f);
                    float h1 = fmaxf(pr - v.z, 0.0f);
                    s[u & 3] += m0 ? h0 : 0.0f;
                    c[u & 3] += m0;
                    s[u & 3] += m1 ? h1 : 0.0f;
                    c[u & 3] += m1;
                }
            }
        }

        float ssum = (s[0] + s[1]) + (s[2] + s[3]);
        int   csum = (c[0] + c[1]) + (c[2] + c[3]);

        #pragma unroll
        for (int o = 16; o > 0; o >>= 1) {
            ssum += __shfl_down_sync(0xFFFFFFFFu, ssum, o);
            csum += __shfl_down_sync(0xFFFFFFFFu, csum, o);
        }

        int w = threadIdx.x >> 5, l = threadIdx.x & 31;
        if (l == 0) { ws[w] = ssum; wc[w] = csum; }
        __syncthreads();
        if (w == 0) {
            ssum = (l < TI / 32) ? ws[l] : 0.0f;
            csum = (l < TI / 32) ? wc[l] : 0;
            #pragma unroll
            for (int o = (TI / 64); o > 0; o >>= 1) {
                ssum += __shfl_down_sync(0xFFFFFFFFu, ssum, o);
                csum += __shfl_down_sync(0xFFFFFFFFu, csum, o);
            }
            if (l == 0) {
                atomicAdd(&g_sum, ssum);
                atomicAdd(&g_cnt, csum);
            }
        }
    }

    // Every block (active or not) takes a ticket; the last one finalizes.
    if (threadIdx.x == 0) {
        __threadfence();
        unsigned old = atomicAdd(&g_ticket, 1u);
        if (old == NBLK - 1) {
            float sum = atomicAdd(&g_sum, 0.0f);   // L2 read, bypasses L1
            int   cnt = atomicAdd(&g_cnt, 0);
            out[0] = (cnt == 0) ? 0.0f : sum / (float)cnt;
            // Reset state for the next call / replay.
            g_sum    = 0.0f;
            g_cnt    = 0;
            g_nc     = 0;
            g_ticket = 0u;
            __threadfence();
        }
    }
}

extern "C" void kernel_launch(void* const* d_in, const int* in_sizes, int n_in,
                              void* d_out, int out_size) {
    // metadata order: z (unused), risk, time, event
    const float* risk  = (const float*)d_in[1];
    const float* timev = (const float*)d_in[2];
    const int*   event = (const int*)d_in[3];
    float* out = (float*)d_out;

    k_compact<<<BN / 256, 256>>>(risk, timev, event);
    dim3 grid(GX, GY);
    k_main<<<grid, TI>>>(risk, timev, out);
}

// round 6
// speedup vs baseline: 1.4443x; 1.4443x over previous
#include <cuda_runtime.h>
#include <cuda_bf16.h>

#define BN 8192
#define MARGIN 1.0f
#define TI 256              // threads per block == i-rows per block
#define TJ 256              // j entries per shared tile
#define GX (BN / TI)        // 32
#define GY (BN / TJ)        // 32
#define NBLK (GX * GY)      // 1024
#define BIGF 1.2676506002282294e30f   // 2^100, exact power of two

typedef unsigned long long ull;

__device__ __forceinline__ ull addf2(ull a, ull b) {
    ull r; asm("add.rn.f32x2 %0, %1, %2;" : "=l"(r) : "l"(a), "l"(b)); return r;
}
__device__ __forceinline__ ull packf2(float lo, float hi) {
    ull r; asm("mov.b64 %0, {%1, %2};" : "=l"(r) : "f"(lo), "f"(hi)); return r;
}
__device__ __forceinline__ void unpackf2(float& lo, float& hi, ull v) {
    asm("mov.b64 {%0, %1}, %2;" : "=f"(lo), "=f"(hi) : "l"(v));
}

// Allocation-free scratch (zero-initialized at load; finalizer resets each call).
__device__ float    g_sum;
__device__ int      g_cnt;
__device__ int      g_nc;
__device__ unsigned g_ticket;
__device__ float    c_risk[BN];
__device__ float    c_time[BN];

// Compact rows with event==1 into c_risk/c_time (order irrelevant for the sum).
__global__ void k_compact(const float* __restrict__ risk,
                          const float* __restrict__ timev,
                          const int*   __restrict__ event) {
    int idx = blockIdx.x * blockDim.x + threadIdx.x;
    if (idx >= BN) return;
    bool p = (event[idx] == 1);
    unsigned m = __ballot_sync(0xFFFFFFFFu, p);
    int lane   = threadIdx.x & 31;
    int leader = __ffs(m) - 1;
    int base = 0;
    if (m != 0u && lane == leader)
        base = atomicAdd(&g_nc, __popc(m));
    base = __shfl_sync(0xFFFFFFFFu, base, (leader < 0 ? 0 : leader));
    if (p) {
        int pos = base + __popc(m & ((1u << lane) - 1u));
        c_risk[pos] = risk[idx];
        c_time[pos] = timev[idx];
    }
}

__global__ void __launch_bounds__(TI)
k_main(const float* __restrict__ risk,
       const float* __restrict__ timev,
       float* __restrict__ out) {
    // Interleaved tile: float4 g holds (tjB[2g], tjB[2g+1], -r[2g], -r[2g+1])
    __shared__ __align__(16) float4 sj4[TJ / 2];
    __shared__ float ws[TI / 32];
    __shared__ float wc[TI / 32];

    const int  nc     = g_nc;
    const bool active = (blockIdx.x * TI) < nc;   // uniform per block

    if (active) {
        // Stage tile: one j per thread (TI == TJ)
        {
            const int t  = threadIdx.x;
            const int j0 = blockIdx.y * TJ;
            float tjB = timev[j0 + t] * BIGF;   // exact: *2^100
            float nr  = -risk[j0 + t];
            float* st = reinterpret_cast<float*>(sj4);
            int g = t >> 1, o = t & 1;
            st[g * 4 + o]     = tjB;
            st[g * 4 + 2 + o] = nr;
        }
        __syncthreads();

        const int i = blockIdx.x * TI + threadIdx.x;

        ull s2a = 0ull, s2b = 0ull;   // packed {f32,f32} hinge sums (0ull == {0.f,0.f})
        ull c2a = 0ull, c2b = 0ull;   // packed {f32,f32} counts

        if (i < nc) {
            const float pr  = MARGIN + c_risk[i];   // hinge = max(pr - r_j, 0)
            const float tbB = c_time[i] * BIGF;     // exact scaling
            const ull ntb2 = packf2(-tbB, -tbB);
            const ull pr2  = packf2(pr, pr);

            #pragma unroll 8
            for (int g = 0; g < TJ / 2; ++g) {
                float4 v = sj4[g];                    // LDS.128 broadcast
                ull dt2 = addf2(packf2(v.x, v.y), ntb2);  // {tjB - tbB} x2, exact sign
                ull dd2 = addf2(packf2(v.z, v.w), pr2);   // {pr - r_j}  x2
                float dt0, dt1, d0, d1;
                unpackf2(dt0, dt1, dt2);
                unpackf2(d0,  d1,  dd2);
                // masked hinge: dtB is 0, or |dtB| >= ~2^77 >> |pr-r|, so
                // max(min(dtB, d), 0) == (t_i < t_j) ? max(d,0) : 0   exactly.
                float h0 = fmaxf(fminf(dt0, d0), 0.0f);
                float h1 = fmaxf(fminf(dt1, d1), 0.0f);
                // mask as float: saturate(dtB) in {0,1} exactly.
                float m0 = __saturatef(dt0);
                float m1 = __saturatef(dt1);
                if (g & 1) { s2b = addf2(s2b, packf2(h0, h1));
                             c2b = addf2(c2b, packf2(m0, m1)); }
                else       { s2a = addf2(s2a, packf2(h0, h1));
                             c2a = addf2(c2a, packf2(m0, m1)); }
            }
        }

        float sl, sh, cl, ch, sl2, sh2, cl2, ch2;
        unpackf2(sl, sh, s2a);  unpackf2(sl2, sh2, s2b);
        unpackf2(cl, ch, c2a);  unpackf2(cl2, ch2, c2b);
        float ssum = (sl + sh) + (sl2 + sh2);
        float csum = (cl + ch) + (cl2 + ch2);   // <= 256 per thread, exact

        #pragma unroll
        for (int o = 16; o > 0; o >>= 1) {
            ssum += __shfl_down_sync(0xFFFFFFFFu, ssum, o);
            csum += __shfl_down_sync(0xFFFFFFFFu, csum, o);
        }

        int w = threadIdx.x >> 5, l = threadIdx.x & 31;
        if (l == 0) { ws[w] = ssum; wc[w] = csum; }
        __syncthreads();
        if (w == 0) {
            ssum = (l < TI / 32) ? ws[l] : 0.0f;
            csum = (l < TI / 32) ? wc[l] : 0.0f;
            #pragma unroll
            for (int o = (TI / 64); o > 0; o >>= 1) {
                ssum += __shfl_down_sync(0xFFFFFFFFu, ssum, o);
                csum += __shfl_down_sync(0xFFFFFFFFu, csum, o);
            }
            if (l == 0) {
                atomicAdd(&g_sum, ssum);
                atomicAdd(&g_cnt, __float2int_rn(csum));  // block count <= 65536: exact
            }
        }
    }

    // Every block takes a ticket; the last one finalizes and resets.
    if (threadIdx.x == 0) {
        __threadfence();
        unsigned old = atomicAdd(&g_ticket, 1u);
        if (old == NBLK - 1) {
            float sum = atomicAdd(&g_sum, 0.0f);   // L2 read
            int   cnt = atomicAdd(&g_cnt, 0);
            out[0] = (cnt == 0) ? 0.0f : sum / (float)cnt;
            g_sum    = 0.0f;
            g_cnt    = 0;
            g_nc     = 0;
            g_ticket = 0u;
            __threadfence();
        }
    }
}

extern "C" void kernel_launch(void* const* d_in, const int* in_sizes, int n_in,
                              void* d_out, int out_size) {
    // metadata order: z (unused), risk, time, event
    const float* risk  = (const float*)d_in[1];
    const float* timev = (const float*)d_in[2];
    const int*   event = (const int*)d_in[3];
    float* out = (float*)d_out;

    k_compact<<<BN / 256, 256>>>(risk, timev, event);
    dim3 grid(GX, GY);
    k_main<<<grid, TI>>>(risk, timev, out);
}